// round 15
// baseline (speedup 1.0000x reference)
#include <cuda_runtime.h>
#include <math.h>
#include <stdint.h>

#define Bb 2
#define Tt 512
#define Cc 768
#define Hh 12
#define HS 64
#define BHn (Bb*Hh)

typedef unsigned long long ull;

// scratch (allocation-free rule: __device__ globals)
__device__ float g_q[BHn*Tt*HS];
__device__ float g_k[BHn*Tt*HS];
__device__ float g_v[BHn*Tt*HS];
__device__ float g_y[Bb*Tt*Cc];
__device__ float g_s[(size_t)BHn*Tt*Tt];   // causal sim matrix per head
__device__ float g_coef[(size_t)BHn*Tt*9];
__device__ int   g_rows[(size_t)BHn*Tt*9];

// lexicographic pairs (a<b) over 8 slots, matching itertools.combinations order
__constant__ int cPA[28] = {0,0,0,0,0,0,0,1,1,1,1,1,1,2,2,2,2,2,3,3,3,3,4,4,4,5,5,6};
__constant__ int cPB[28] = {1,2,3,4,5,6,7,2,3,4,5,6,7,3,4,5,6,7,4,5,6,7,5,6,7,6,7,7};

// 54 dot-tasks: 45 gram pairs (r<=c) + 9 q-dots (c==9 means q)
__constant__ int cTR[54] = {0,0,0,0,0,0,0,0,0, 1,1,1,1,1,1,1,1, 2,2,2,2,2,2,2,
                            3,3,3,3,3,3, 4,4,4,4,4, 5,5,5,5, 6,6,6, 7,7, 8,
                            0,1,2,3,4,5,6,7,8};
__constant__ int cTC[54] = {0,1,2,3,4,5,6,7,8, 1,2,3,4,5,6,7,8, 2,3,4,5,6,7,8,
                            3,4,5,6,7,8, 4,5,6,7,8, 5,6,7,8, 6,7,8, 7,8, 8,
                            9,9,9,9,9,9,9,9,9};

// ---------------------------------------------------------------------------
// packed dual-fp32 FMA helpers (sims kernel)
// ---------------------------------------------------------------------------
__device__ __forceinline__ ull pk2(float x) {
    ull r; uint32_t b = __float_as_uint(x);
    asm("mov.b64 %0, {%1, %1};" : "=l"(r) : "r"(b));
    return r;
}
__device__ __forceinline__ void ffma2(ull& acc, ull a, ull b) {
    asm("fma.rn.f32x2 %0, %1, %2, %0;" : "+l"(acc) : "l"(a), "l"(b));
}
__device__ __forceinline__ float lo32(ull v) { return __uint_as_float((uint32_t)v); }
__device__ __forceinline__ float hi32(ull v) { return __uint_as_float((uint32_t)(v >> 32)); }

// ---------------------------------------------------------------------------
// qkv-part GEMM (fp32): C = x·W_attnᵀ + b for n in [nbase, nbase+64*gridDim.x)
// 64x64 tile, 128 threads, 8x4 micro-tile, BK=16, dbl-buffer. Scatter q/k/v.
// ---------------------------------------------------------------------------
#define GBK 16
#define GNC (Cc/GBK)   // 48

__global__ void __launch_bounds__(128) gemm_qkv_part(
    const float* __restrict__ A,     // x [1024,768]
    const float* __restrict__ Bm,    // W_attn [2304,768]
    const float* __restrict__ bias,  // b_attn
    int nbase)
{
    const int K = Cc;
    __shared__ __align__(16) float As[2][GBK][64+4];
    __shared__ __align__(16) float Bs[2][GBK][64+4];
    const int tid = threadIdx.x;
    const int tx = tid & 15, ty = tid >> 4;     // ty 0..7
    const int m0 = blockIdx.y * 64, n0 = nbase + blockIdx.x * 64;

    const int lr = tid >> 2;            // 0..31 (+32 second half)
    const int lc = (tid & 3) << 2;
    const float* Ap = A  + (size_t)(m0 + lr)*K + lc;
    const float* Bp = Bm + (size_t)(n0 + lr)*K + lc;

    float4 ra0, ra1, rb0, rb1;
    ra0 = *(const float4*)(Ap);
    ra1 = *(const float4*)(Ap + (size_t)32*K);
    rb0 = *(const float4*)(Bp);
    rb1 = *(const float4*)(Bp + (size_t)32*K);
    {
        As[0][lc+0][lr]=ra0.x; As[0][lc+1][lr]=ra0.y; As[0][lc+2][lr]=ra0.z; As[0][lc+3][lr]=ra0.w;
        As[0][lc+0][32+lr]=ra1.x; As[0][lc+1][32+lr]=ra1.y; As[0][lc+2][32+lr]=ra1.z; As[0][lc+3][32+lr]=ra1.w;
        Bs[0][lc+0][lr]=rb0.x; Bs[0][lc+1][lr]=rb0.y; Bs[0][lc+2][lr]=rb0.z; Bs[0][lc+3][lr]=rb0.w;
        Bs[0][lc+0][32+lr]=rb1.x; Bs[0][lc+1][32+lr]=rb1.y; Bs[0][lc+2][32+lr]=rb1.z; Bs[0][lc+3][32+lr]=rb1.w;
    }
    __syncthreads();

    float acc[8][4];
#pragma unroll
    for (int i=0;i<8;i++)
#pragma unroll
      for (int j=0;j<4;j++) acc[i][j]=0.f;

    int cur = 0;
    for (int kc = 0; kc < GNC; kc++) {
        if (kc + 1 < GNC) {
            int k0 = (kc + 1) * GBK;
            ra0 = *(const float4*)(Ap + k0);
            ra1 = *(const float4*)(Ap + (size_t)32*K + k0);
            rb0 = *(const float4*)(Bp + k0);
            rb1 = *(const float4*)(Bp + (size_t)32*K + k0);
        }
#pragma unroll
        for (int kk = 0; kk < GBK; kk++) {
            float4 a0 = *(const float4*)&As[cur][kk][ty<<2];
            float4 a1 = *(const float4*)&As[cur][kk][32+(ty<<2)];
            float4 b  = *(const float4*)&Bs[cur][kk][tx<<2];
            float av[8] = {a0.x,a0.y,a0.z,a0.w, a1.x,a1.y,a1.z,a1.w};
#pragma unroll
            for (int i = 0; i < 8; i++) {
                acc[i][0] += av[i]*b.x;
                acc[i][1] += av[i]*b.y;
                acc[i][2] += av[i]*b.z;
                acc[i][3] += av[i]*b.w;
            }
        }
        if (kc + 1 < GNC) {
            int nb = cur ^ 1;
            As[nb][lc+0][lr]=ra0.x; As[nb][lc+1][lr]=ra0.y; As[nb][lc+2][lr]=ra0.z; As[nb][lc+3][lr]=ra0.w;
            As[nb][lc+0][32+lr]=ra1.x; As[nb][lc+1][32+lr]=ra1.y; As[nb][lc+2][32+lr]=ra1.z; As[nb][lc+3][32+lr]=ra1.w;
            Bs[nb][lc+0][lr]=rb0.x; Bs[nb][lc+1][lr]=rb0.y; Bs[nb][lc+2][lr]=rb0.z; Bs[nb][lc+3][lr]=rb0.w;
            Bs[nb][lc+0][32+lr]=rb1.x; Bs[nb][lc+1][32+lr]=rb1.y; Bs[nb][lc+2][32+lr]=rb1.z; Bs[nb][lc+3][32+lr]=rb1.w;
        }
        __syncthreads();
        cur ^= 1;
    }

#pragma unroll
    for (int im = 0; im < 8; im++) {
        int m = m0 + ((im < 4) ? ((ty<<2) + im) : (32 + (ty<<2) + im - 4));
        int b = m >> 9, t = m & 511;
#pragma unroll
        for (int j = 0; j < 4; j++) {
            int n = n0 + (tx<<2) + j;
            float val = acc[im][j] + bias[n];
            int part = n / Cc;
            int c = n - part*Cc;
            int h = c >> 6;
            int d = c & 63;
            float* dst = (part==0) ? g_q : (part==1) ? g_k : g_v;
            dst[(((size_t)(b*Hh + h))*Tt + t)*HS + d] = val;
        }
    }
}

// ---------------------------------------------------------------------------
// zero kernel for out (proj accumulates via atomicAdd)
// ---------------------------------------------------------------------------
__global__ void __launch_bounds__(256) zero_out_kernel(float* __restrict__ out) {
    int idx = blockIdx.x * 256 + threadIdx.x;
    ((float4*)out)[idx] = make_float4(0.f, 0.f, 0.f, 0.f);
}

// ---------------------------------------------------------------------------
// proj GEMM (fp32, split-K=2): out += g_y·W_projᵀ (+ b on split 0)
// ---------------------------------------------------------------------------
#define PKS (Cc/2)
#define PNC2 (PKS/GBK)   // 24

__global__ void __launch_bounds__(128) gemm_proj_kernel(
    const float* __restrict__ Bm,
    const float* __restrict__ bias,
    float* __restrict__ out)
{
    const int K = Cc;
    const float* A = g_y;
    __shared__ __align__(16) float As[2][GBK][64+4];
    __shared__ __align__(16) float Bs[2][GBK][64+4];
    const int tid = threadIdx.x;
    const int tx = tid & 15, ty = tid >> 4;
    const int m0 = blockIdx.y * 64, n0 = blockIdx.x * 64;
    const int kbase = blockIdx.z * PKS;

    const int lr = tid >> 2;
    const int lc = (tid & 3) << 2;
    const float* Ap = A  + (size_t)(m0 + lr)*K + kbase + lc;
    const float* Bp = Bm + (size_t)(n0 + lr)*K + kbase + lc;

    float4 ra0, ra1, rb0, rb1;
    ra0 = *(const float4*)(Ap);
    ra1 = *(const float4*)(Ap + (size_t)32*K);
    rb0 = *(const float4*)(Bp);
    rb1 = *(const float4*)(Bp + (size_t)32*K);
    {
        As[0][lc+0][lr]=ra0.x; As[0][lc+1][lr]=ra0.y; As[0][lc+2][lr]=ra0.z; As[0][lc+3][lr]=ra0.w;
        As[0][lc+0][32+lr]=ra1.x; As[0][lc+1][32+lr]=ra1.y; As[0][lc+2][32+lr]=ra1.z; As[0][lc+3][32+lr]=ra1.w;
        Bs[0][lc+0][lr]=rb0.x; Bs[0][lc+1][lr]=rb0.y; Bs[0][lc+2][lr]=rb0.z; Bs[0][lc+3][lr]=rb0.w;
        Bs[0][lc+0][32+lr]=rb1.x; Bs[0][lc+1][32+lr]=rb1.y; Bs[0][lc+2][32+lr]=rb1.z; Bs[0][lc+3][32+lr]=rb1.w;
    }
    __syncthreads();

    float acc[8][4];
#pragma unroll
    for (int i=0;i<8;i++)
#pragma unroll
      for (int j=0;j<4;j++) acc[i][j]=0.f;

    int cur = 0;
    for (int kc = 0; kc < PNC2; kc++) {
        if (kc + 1 < PNC2) {
            int k0 = (kc + 1) * GBK;
            ra0 = *(const float4*)(Ap + k0);
            ra1 = *(const float4*)(Ap + (size_t)32*K + k0);
            rb0 = *(const float4*)(Bp + k0);
            rb1 = *(const float4*)(Bp + (size_t)32*K + k0);
        }
#pragma unroll
        for (int kk = 0; kk < GBK; kk++) {
            float4 a0 = *(const float4*)&As[cur][kk][ty<<2];
            float4 a1 = *(const float4*)&As[cur][kk][32+(ty<<2)];
            float4 b  = *(const float4*)&Bs[cur][kk][tx<<2];
            float av[8] = {a0.x,a0.y,a0.z,a0.w, a1.x,a1.y,a1.z,a1.w};
#pragma unroll
            for (int i = 0; i < 8; i++) {
                acc[i][0] += av[i]*b.x;
                acc[i][1] += av[i]*b.y;
                acc[i][2] += av[i]*b.z;
                acc[i][3] += av[i]*b.w;
            }
        }
        if (kc + 1 < PNC2) {
            int nb = cur ^ 1;
            As[nb][lc+0][lr]=ra0.x; As[nb][lc+1][lr]=ra0.y; As[nb][lc+2][lr]=ra0.z; As[nb][lc+3][lr]=ra0.w;
            As[nb][lc+0][32+lr]=ra1.x; As[nb][lc+1][32+lr]=ra1.y; As[nb][lc+2][32+lr]=ra1.z; As[nb][lc+3][32+lr]=ra1.w;
            Bs[nb][lc+0][lr]=rb0.x; Bs[nb][lc+1][lr]=rb0.y; Bs[nb][lc+2][lr]=rb0.z; Bs[nb][lc+3][lr]=rb0.w;
            Bs[nb][lc+0][32+lr]=rb1.x; Bs[nb][lc+1][32+lr]=rb1.y; Bs[nb][lc+2][32+lr]=rb1.z; Bs[nb][lc+3][32+lr]=rb1.w;
        }
        __syncthreads();
        cur ^= 1;
    }

    const bool addb = (blockIdx.z == 0);
#pragma unroll
    for (int im = 0; im < 8; im++) {
        int m = m0 + ((im < 4) ? ((ty<<2) + im) : (32 + (ty<<2) + im - 4));
        int n = n0 + (tx<<2);
        float* dst = out + (size_t)m*Cc + n;
#pragma unroll
        for (int j = 0; j < 4; j++) {
            float val = acc[im][j] + (addb ? bias[n+j] : 0.f);
            atomicAdd(dst + j, val);
        }
    }
}

// ---------------------------------------------------------------------------
// sims kernel (fp32, FFMA2): S[h][i][j] = q_i·k_j, lower-triangular blocks
// ---------------------------------------------------------------------------
#define SBK 16

__global__ void __launch_bounds__(256) sims_kernel() {
    if (blockIdx.x > blockIdx.y) return;
    const int head = blockIdx.z;
    const int m0 = blockIdx.y * 64;
    const int n0 = blockIdx.x * 64;
    const float* Qh = g_q + (size_t)head*Tt*HS;
    const float* Kh = g_k + (size_t)head*Tt*HS;
    float* Sh = g_s + (size_t)head*Tt*Tt;

    __shared__ __align__(16) float As[SBK][64+4];
    __shared__ __align__(16) float Bs[SBK][64+4];
    int tid = threadIdx.x;
    int tx = tid & 15, ty = tid >> 4;
    int lr = tid >> 2;
    int lk = (tid & 3) << 2;
    ull acc2[4][2] = {};
    for (int k0 = 0; k0 < HS; k0 += SBK) {
        float4 av = *(const float4*)(Qh + (size_t)(m0+lr)*HS + k0 + lk);
        float4 bv = *(const float4*)(Kh + (size_t)(n0+lr)*HS + k0 + lk);
        As[lk+0][lr]=av.x; As[lk+1][lr]=av.y; As[lk+2][lr]=av.z; As[lk+3][lr]=av.w;
        Bs[lk+0][lr]=bv.x; Bs[lk+1][lr]=bv.y; Bs[lk+2][lr]=bv.z; Bs[lk+3][lr]=bv.w;
        __syncthreads();
#pragma unroll
        for (int kk = 0; kk < SBK; kk++) {
            float4 a = *(const float4*)&As[kk][ty<<2];
            const ull* bp = (const ull*)&Bs[kk][tx<<2];
            ull b0 = bp[0], b1 = bp[1];
            ull a0 = pk2(a.x), a1 = pk2(a.y), a2 = pk2(a.z), a3 = pk2(a.w);
            ffma2(acc2[0][0], a0, b0); ffma2(acc2[0][1], a0, b1);
            ffma2(acc2[1][0], a1, b0); ffma2(acc2[1][1], a1, b1);
            ffma2(acc2[2][0], a2, b0); ffma2(acc2[2][1], a2, b1);
            ffma2(acc2[3][0], a3, b0); ffma2(acc2[3][1], a3, b1);
        }
        __syncthreads();
    }
#pragma unroll
    for (int im = 0; im < 4; im++) {
#pragma unroll
        for (int jp = 0; jp < 2; jp++) {
            int m = m0 + (ty<<2) + im;
            int n = n0 + (tx<<2) + (jp<<1);
            Sh[(size_t)m*Tt + n  ] = lo32(acc2[im][jp]);
            Sh[(size_t)m*Tt + n+1] = hi32(acc2[im][jp]);
        }
    }
}

// ---------------------------------------------------------------------------
// DPP score1: WARP per (token, head). Selection + coeffs (no v access).
// ---------------------------------------------------------------------------
#define NW 8
#define FULLMASK 0xffffffffu
#define RS (HS+4)

__global__ void __launch_bounds__(256) dpp_score1_kernel() {
    const int lane = threadIdx.x & 31;
    const int w    = threadIdx.x >> 5;
    const int i    = blockIdx.x * NW + w;
    const int head = blockIdx.y;

    const float* qh = g_q + (size_t)head*Tt*HS;
    const float* kh = g_k + (size_t)head*Tt*HS;
    const float* srow = g_s + ((size_t)head*Tt + i)*Tt;

    __shared__ __align__(16) float skr[NW][10][RS];   // 9 k rows + q row (idx 9)
    __shared__ float sG[NW][9][9];
    __shared__ float sdv[NW][9];
    __shared__ int   sRows[NW][9];
    __shared__ float sCoeff[NW][9];

    float sv[16];
#pragma unroll
    for (int c4 = 0; c4 < 4; c4++) {
        float4 t = ((const float4*)srow)[lane + (c4 << 5)];
        int jb = (lane << 2) + (c4 << 7);
        sv[c4*4+0] = (jb+0 <= i) ? t.x : -INFINITY;
        sv[c4*4+1] = (jb+1 <= i) ? t.y : -INFINITY;
        sv[c4*4+2] = (jb+2 <= i) ? t.z : -INFINITY;
        sv[c4*4+3] = (jb+3 <= i) ? t.w : -INFINITY;
    }

    const int ncand = (i + 1 < 8) ? (i + 1) : 8;

    int top[8];
#pragma unroll
    for (int r = 0; r < 8; r++) {
        float bv = -INFINITY; int bi = 0x7fffffff;
#pragma unroll
        for (int idx = 0; idx < 16; idx++) {
            int j = (lane << 2) + ((idx >> 2) << 7) + (idx & 3);
            float v = sv[idx];
            if (v > bv || (v == bv && j < bi)) { bv = v; bi = j; }
        }
#pragma unroll
        for (int off = 16; off > 0; off >>= 1) {
            float ov = __shfl_xor_sync(FULLMASK, bv, off);
            int   oi = __shfl_xor_sync(FULLMASK, bi, off);
            if (ov > bv || (ov == bv && oi < bi)) { bv = ov; bi = oi; }
        }
        int sel = bi;
        if (sel < 0 || sel > i) sel = 0;
        top[r] = sel;
        if (((sel >> 2) & 31) == lane)
            sv[((sel >> 7) << 2) | (sel & 3)] = -INFINITY;
    }

    if (lane == 0) {
        sRows[w][0] = i;
#pragma unroll
        for (int r = 0; r < 8; r++) sRows[w][r+1] = top[r];
    }
    __syncwarp();

    // stage 9 k rows + q row
    for (int e = lane; e < 9*16; e += 32) {
        int r = e >> 4, f = e & 15;
        int row = sRows[w][r];
        *(float4*)&skr[w][r][f<<2] = ((const float4*)(kh + (size_t)row*HS))[f];
    }
    if (lane < 16)
        *(float4*)&skr[w][9][lane<<2] = ((const float4*)(qh + (size_t)i*HS))[lane];
    __syncwarp();

    {
        int t0 = lane, t1 = lane + 32;
        int r0 = cTR[t0], c0 = cTC[t0];
        int r1 = (t1 < 54) ? cTR[t1] : 0;
        int c1 = (t1 < 54) ? cTC[t1] : 0;
        float a0 = 0.f, a1 = 0.f;
#pragma unroll
        for (int f = 0; f < 16; f++) {
            float4 x0 = *(const float4*)&skr[w][r0][f<<2];
            float4 y0 = *(const float4*)&skr[w][c0][f<<2];
            a0 += x0.x*y0.x + x0.y*y0.y + x0.z*y0.z + x0.w*y0.w;
            float4 x1 = *(const float4*)&skr[w][r1][f<<2];
            float4 y1 = *(const float4*)&skr[w][c1][f<<2];
            a1 += x1.x*y1.x + x1.y*y1.y + x1.z*y1.z + x1.w*y1.w;
        }
        if (c0 == 9) sdv[w][r0] = a0 * 0.125f;
        else { sG[w][r0][c0] = a0; sG[w][c0][r0] = a0; }
        if (t1 < 54) {
            if (c1 == 9) sdv[w][r1] = a1 * 0.125f;
            else { sG[w][r1][c1] = a1; sG[w][c1][r1] = a1; }
        }
    }
    __syncwarp();

    float sc0 = -INFINITY, sc1 = -INFINITY;
    float w00=0,w01=0,w02=0, w10=0,w11=0,w12=0;
    int a0i=-1, b0i=-1, a1i=-1, b1i=-1;
#pragma unroll
    for (int half = 0; half < 2; half++) {
        int cid = lane + (half << 5);
        if (cid >= 36) break;
        int a, b, sz;
        if (cid < 8) { sz = 2; a = cid; b = -1; }
        else         { sz = 3; a = cPA[cid-8]; b = cPB[cid-8]; }
        bool valid = (a < ncand) && (sRows[w][a+1] != i);
        if (b >= 0) valid = valid && (b < ncand) && (sRows[w][b+1] != i);
        float score = -INFINITY, x0 = 0.f, x1 = 0.f, x2 = 0.f;
        if (valid) {
            int ra = a + 1;
            if (sz == 2) {
                float det = sG[w][0][0]*sG[w][ra][ra] - sG[w][0][ra]*sG[w][0][ra];
                score = logf(det + 1e-6f) * 0.5f;
                float d0 = sdv[w][0], d1 = sdv[w][ra];
                float m = fmaxf(d0, d1);
                float e0 = expf(d0-m), e1 = expf(d1-m);
                float inv = 1.f/(e0+e1);
                x0 = e0*inv; x1 = e1*inv;
            } else {
                int rb = b + 1;
                float g00=sG[w][0][0],  g01=sG[w][0][ra],  g02=sG[w][0][rb];
                float g11=sG[w][ra][ra], g12=sG[w][ra][rb], g22=sG[w][rb][rb];
                float det = g00*(g11*g22 - g12*g12)
                          - g01*(g01*g22 - g12*g02)
                          + g02*(g01*g12 - g11*g02);
                score = logf(det + 1e-6f) * (1.f/3.f);
                float d0=sdv[w][0], d1=sdv[w][ra], d2=sdv[w][rb];
                float m = fmaxf(d0, fmaxf(d1, d2));
                float e0=expf(d0-m), e1=expf(d1-m), e2=expf(d2-m);
                float inv = 1.f/(e0+e1+e2);
                x0=e0*inv; x1=e1*inv; x2=e2*inv;
            }
        }
        if (half == 0) { sc0=score; w00=x0; w01=x1; w02=x2; a0i=a; b0i=b; }
        else           { sc1=score; w10=x0; w11=x1; w12=x2; a1i=a; b1i=b; }
    }

    float mx = fmaxf(sc0, sc1);
#pragma unroll
    for (int off = 16; off > 0; off >>= 1)
        mx = fmaxf(mx, __shfl_xor_sync(FULLMASK, mx, off));

    if (lane < 9) sCoeff[w][lane] = 0.f;
    __syncwarp();

    if (mx == -INFINITY) {
        if (lane == 0) sCoeff[w][0] = 1.f;     // no valid subset -> y = v[i]
        __syncwarp();
    } else {
        float p0 = (sc0 == -INFINITY) ? 0.f : expf(sc0 - mx);
        float p1 = (sc1 == -INFINITY) ? 0.f : expf(sc1 - mx);
        float s = p0 + p1;
#pragma unroll
        for (int off = 16; off > 0; off >>= 1)
            s += __shfl_xor_sync(FULLMASK, s, off);
        float invs = 1.f / s;
        if (p0 > 0.f) {
            float p = p0 * invs;
            atomicAdd(&sCoeff[w][0],     p * w00);
            atomicAdd(&sCoeff[w][a0i+1], p * w01);
            if (b0i >= 0) atomicAdd(&sCoeff[w][b0i+1], p * w02);
        }
        if (p1 > 0.f) {
            float p = p1 * invs;
            atomicAdd(&sCoeff[w][0],     p * w10);
            atomicAdd(&sCoeff[w][a1i+1], p * w11);
            if (b1i >= 0) atomicAdd(&sCoeff[w][b1i+1], p * w12);
        }
        __syncwarp();
    }

    if (lane < 9) {
        size_t o = ((size_t)head*Tt + i)*9 + lane;
        g_coef[o] = sCoeff[w][lane];
        g_rows[o] = sRows[w][lane];
    }
}

// ---------------------------------------------------------------------------
// DPP score2: y = sum_r coeff[r]*v[row_r]  (warp per token,head)
// ---------------------------------------------------------------------------
__global__ void __launch_bounds__(256) dpp_y_kernel() {
    const int lane = threadIdx.x & 31;
    const int w    = threadIdx.x >> 5;
    const int i    = blockIdx.x * NW + w;
    const int head = blockIdx.y;

    __shared__ float sC[NW][9];
    __shared__ int   sR[NW][9];
    size_t o = ((size_t)head*Tt + i)*9;
    if (lane < 9) { sC[w][lane] = g_coef[o+lane]; sR[w][lane] = g_rows[o+lane]; }
    __syncwarp();

    const float* vh = g_v + (size_t)head*Tt*HS;
    int bb = head / Hh, h = head - bb*Hh;
    float* ybase = g_y + ((size_t)(bb*Tt + i))*Cc + h*HS;
#pragma unroll
    for (int half = 0; half < 2; half++) {
        int d = lane + (half << 5);
        float y = 0.f;
#pragma unroll
        for (int r = 0; r < 9; r++) y += sC[w][r] * vh[(size_t)sR[w][r]*HS + d];
        ybase[d] = y;
    }
}

// ---------------------------------------------------------------------------
extern "C" void kernel_launch(void* const* d_in, const int* in_sizes, int n_in,
                              void* d_out, int out_size) {
    const float* x      = (const float*)d_in[0];
    const float* W_attn = (const float*)d_in[1];
    const float* b_attn = (const float*)d_in[2];
    const float* W_proj = (const float*)d_in[3];
    const float* b_proj = (const float*)d_in[4];
    float* out = (float*)d_out;

    // fresh stream/events each call (no device memory involved; capture-safe fork/join)
    cudaStream_t s1;
    cudaStreamCreateWithFlags(&s1, cudaStreamNonBlocking);
    cudaEvent_t evFork, evQK, evV;
    cudaEventCreateWithFlags(&evFork, cudaEventDisableTiming);
    cudaEventCreateWithFlags(&evQK,   cudaEventDisableTiming);
    cudaEventCreateWithFlags(&evV,    cudaEventDisableTiming);

    // fork s1 from the capture (legacy) stream
    cudaEventRecord(evFork, 0);
    cudaStreamWaitEvent(s1, evFork, 0);

    // s1: zero the output early (proj accumulates)
    zero_out_kernel<<<(Bb*Tt*Cc/4)/256, 256, 0, s1>>>(out);

    // s0: q,k GEMM (selection-critical prefix of the chain)
    dim3 gqk(2*Cc/64, Bb*Tt/64);          // 24 x 16 = 384 blocks
    gemm_qkv_part<<<gqk, 128>>>(x, W_attn, b_attn, 0);
    cudaEventRecord(evQK, 0);

    // s1: v GEMM after qk (overlaps with sims + score1 below)
    cudaStreamWaitEvent(s1, evQK, 0);
    dim3 gv(Cc/64, Bb*Tt/64);             // 12 x 16 = 192 blocks
    gemm_qkv_part<<<gv, 128, 0, s1>>>(x, W_attn, b_attn, 2*Cc);
    cudaEventRecord(evV, s1);

    // s0: sims + selection/coeffs (no v dependence)
    dim3 gs(Tt/64, Tt/64, BHn);
    sims_kernel<<<gs, 256>>>();
    dim3 g2(Tt/NW, BHn);
    dpp_score1_kernel<<<g2, 256>>>();

    // join: y needs v
    cudaStreamWaitEvent(0, evV, 0);
    dpp_y_kernel<<<g2, 256>>>();

    dim3 g3(Cc/64, Bb*Tt/64, 2);          // 12 x 16 x 2 = 384 blocks
    gemm_proj_kernel<<<g3, 128>>>(W_proj, b_proj, out);
}